// round 17
// baseline (speedup 1.0000x reference)
#include <cuda_runtime.h>
#include <cuda_bf16.h>
#include <cuda_fp16.h>
#include <cstdint>

#define UU 200000
#define NN 50000
#define EE 1600000

// Scratch (static __device__ arrays; allocation APIs are forbidden)
// P/Q stored as bf16x2-packed rows: word w of row = (k=2w, k=2w+1)
__device__ uint32_t g_Pb[(size_t)UU * 32];
__device__ uint32_t g_Qb[(size_t)NN * 32];
__device__ float    g_ex[EE];                       // exp(logit) per edge
__device__ int      g_rs[NN + 1];                   // row_start per node
__device__ unsigned short g_u2eh[(size_t)UU * 64];  // fp16 copy of u2e (agg reads)
// Weights (bf16) pre-packed in m16n8k16 B-fragment order.
// word[(nt*32 + lane)*8 + ks*2 + reg] (reg0: k=ks*16+tg*2, reg1: +8)
__device__ uint32_t g_W2f[2048];
__device__ uint32_t g_W1tf[2048];  // W1 rows 0..63
__device__ uint32_t g_W1bf[2048];  // W1 rows 64..127

// ================= helpers =================
__device__ __forceinline__ unsigned short f2bf(float x) {
    __nv_bfloat16 b = __float2bfloat16_rn(x);
    return *reinterpret_cast<unsigned short*>(&b);
}
// pack pair (a,b) to bf16x2 word (a in low half)
__device__ __forceinline__ uint32_t cvt2(float a, float b) {
    uint32_t r;
    asm("cvt.rn.bf16x2.f32 %0, %1, %2;" : "=r"(r) : "f"(b), "f"(a));
    return r;
}
// pack pair (a,b) to fp16x2 word (a in low half)
__device__ __forceinline__ uint32_t cvth2(float a, float b) {
    __half2 h = __floats2half2_rn(a, b);
    return *reinterpret_cast<uint32_t*>(&h);
}
// bf16x2 relu(a + b)
__device__ __forceinline__ uint32_t hreluadd2(uint32_t a, uint32_t b) {
    __nv_bfloat162 s = __hadd2(*reinterpret_cast<__nv_bfloat162*>(&a),
                               *reinterpret_cast<__nv_bfloat162*>(&b));
    __nv_bfloat162 z = __float2bfloat162_rn(0.f);
    __nv_bfloat162 m = __hmax2(s, z);
    return *reinterpret_cast<uint32_t*>(&m);
}
// unpack 4 fp16 (uint2) -> float4
__device__ __forceinline__ float4 h4tof4(uint2 u) {
    __half2 a = *reinterpret_cast<__half2*>(&u.x);
    __half2 b = *reinterpret_cast<__half2*>(&u.y);
    float2 fa = __half22float2(a), fb = __half22float2(b);
    return make_float4(fa.x, fa.y, fb.x, fb.y);
}

// D(16x8,f32) += A(16x16,bf16,row) x B(16x8,bf16,col)
__device__ __forceinline__ void mma_bf16(float (&c)[4],
    uint32_t a0, uint32_t a1, uint32_t a2, uint32_t a3,
    uint32_t b0, uint32_t b1)
{
    asm volatile(
        "mma.sync.aligned.m16n8k16.row.col.f32.bf16.bf16.f32 "
        "{%0,%1,%2,%3}, {%4,%5,%6,%7}, {%8,%9}, {%0,%1,%2,%3};"
        : "+f"(c[0]), "+f"(c[1]), "+f"(c[2]), "+f"(c[3])
        : "r"(a0), "r"(a1), "r"(a2), "r"(a3), "r"(b0), "r"(b1));
}

// 4 MMAs for one n-tile (K=64, single product)
__device__ __forceinline__ void mma_1p_ntile(float (&acc)[4],
    const uint32_t (&a)[4][4], uint4 b0, uint4 b1)
{
    mma_bf16(acc, a[0][0], a[0][1], a[0][2], a[0][3], b0.x, b0.y);
    mma_bf16(acc, a[1][0], a[1][1], a[1][2], a[1][3], b0.z, b0.w);
    mma_bf16(acc, a[2][0], a[2][1], a[2][2], a[2][3], b1.x, b1.y);
    mma_bf16(acc, a[3][0], a[3][1], a[3][2], a[3][3], b1.z, b1.w);
}

// ldmatrix x4: one m16k16 bf16 A-fragment (4 regs) in one instruction
__device__ __forceinline__ void ldsm_x4(uint32_t (&a)[4], uint32_t addr) {
    asm volatile("ldmatrix.sync.aligned.m8n8.x4.shared.b16 {%0,%1,%2,%3}, [%4];"
        : "=r"(a[0]), "=r"(a[1]), "=r"(a[2]), "=r"(a[3]) : "r"(addr));
}

// ============================================================
// prep_all: pack W2 / W1-top / W1-bottom into bf16 B-fragment order.
// grid 24 x 256: blocks [0,8) -> W2, [8,16) -> W1t, [16,24) -> W1b
// ============================================================
__global__ void prep_all(const float* __restrict__ W1, const float* __restrict__ W2)
{
    int which = blockIdx.x >> 3;
    int i = (blockIdx.x & 7) * 256 + threadIdx.x;
    const float* W = (which == 0) ? W2 : (which == 1 ? W1 : W1 + 64 * 64);
    uint32_t* dst  = (which == 0) ? g_W2f : (which == 1 ? g_W1tf : g_W1bf);
    int nt = i >> 8, L = (i >> 3) & 31, w = i & 7;
    int ks = w >> 1, reg = w & 1;
    int g = L >> 2, tg = L & 3;
    int n = nt * 8 + g;
    int k = ks * 16 + reg * 8 + tg * 2;
    float v0 = __ldg(W + k * 64 + n);
    float v1 = __ldg(W + (k + 1) * 64 + n);
    dst[i] = (uint32_t)f2bf(v0) | ((uint32_t)f2bf(v1) << 16);
}

// ============================================================
// rowgemm_mma: outb[r] = bf16( src[gather?gth[r]:r] @ W(64x64) (+ bias) )
// A-fragments built directly from global; 256 threads = 8 warps,
// 32 rows/warp (two m16 frag sets sharing B loads), 256 rows/block.
// WRITEH: also emit fp16 copy of src rows into g_u2eh (P pass only).
// ============================================================
template <bool GATHER, bool BIAS, bool WRITEH>
__global__ void __launch_bounds__(256) rowgemm_mma(
    const float* __restrict__ src, const int* __restrict__ gth,
    const uint32_t* __restrict__ Bf, const float* __restrict__ bias,
    uint32_t* __restrict__ outb, int rows)
{
    int tid = threadIdx.x;
    int wid = tid >> 5, lane = tid & 31;
    int g = lane >> 2, tg = lane & 3;
    int r0 = blockIdx.x * 256;

    int row[4];
    const float* R[4];
#pragma unroll
    for (int j = 0; j < 4; j++) {
        row[j] = r0 + wid * 32 + g + j * 8;
        int cr = min(row[j], rows - 1);
        long s = GATHER ? (long)__ldg(gth + cr) : (long)cr;
        R[j] = src + s * 64 + tg * 2;
    }

    uint32_t a0[4][4], a1[4][4];
#pragma unroll
    for (int ks = 0; ks < 4; ks++) {
        int kb = ks * 16;
        float2 x0 = __ldg((const float2*)(R[0] + kb));
        float2 x1 = __ldg((const float2*)(R[1] + kb));
        float2 x2 = __ldg((const float2*)(R[2] + kb));
        float2 x3 = __ldg((const float2*)(R[3] + kb));
        float2 y0 = __ldg((const float2*)(R[0] + kb + 8));
        float2 y1 = __ldg((const float2*)(R[1] + kb + 8));
        float2 y2 = __ldg((const float2*)(R[2] + kb + 8));
        float2 y3 = __ldg((const float2*)(R[3] + kb + 8));
        a0[ks][0] = cvt2(x0.x, x0.y);
        a0[ks][1] = cvt2(x1.x, x1.y);
        a0[ks][2] = cvt2(y0.x, y0.y);
        a0[ks][3] = cvt2(y1.x, y1.y);
        a1[ks][0] = cvt2(x2.x, x2.y);
        a1[ks][1] = cvt2(x3.x, x3.y);
        a1[ks][2] = cvt2(y2.x, y2.y);
        a1[ks][3] = cvt2(y3.x, y3.y);
        if (WRITEH) {
            // fp16 copy: lane owns words ks*8+tg (x) and ks*8+4+tg (y) of each row
            uint32_t* H0 = (uint32_t*)(g_u2eh + (size_t)row[0] * 64);
            uint32_t* H1 = (uint32_t*)(g_u2eh + (size_t)row[1] * 64);
            uint32_t* H2 = (uint32_t*)(g_u2eh + (size_t)row[2] * 64);
            uint32_t* H3 = (uint32_t*)(g_u2eh + (size_t)row[3] * 64);
            int wA = ks * 8 + tg, wB = wA + 4;
            if (row[0] < rows) { H0[wA] = cvth2(x0.x, x0.y); H0[wB] = cvth2(y0.x, y0.y); }
            if (row[1] < rows) { H1[wA] = cvth2(x1.x, x1.y); H1[wB] = cvth2(y1.x, y1.y); }
            if (row[2] < rows) { H2[wA] = cvth2(x2.x, x2.y); H2[wB] = cvth2(y2.x, y2.y); }
            if (row[3] < rows) { H3[wA] = cvth2(x3.x, x3.y); H3[wB] = cvth2(y3.x, y3.y); }
        }
    }

#pragma unroll
    for (int nt = 0; nt < 8; nt++) {
        const uint4* B = (const uint4*)(Bf + (nt * 32 + lane) * 8);
        uint4 bw0 = __ldg(B), bw1 = __ldg(B + 1);
        float acc0[4] = {0.f, 0.f, 0.f, 0.f};
        float acc1[4] = {0.f, 0.f, 0.f, 0.f};
        mma_1p_ntile(acc0, a0, bw0, bw1);
        mma_1p_ntile(acc1, a1, bw0, bw1);
        int c0 = nt * 8 + tg * 2;
        float b0v = 0.f, b1v = 0.f;
        if (BIAS) {
            float2 bv = __ldg((const float2*)(bias + c0));
            b0v = bv.x; b1v = bv.y;
        }
        int wrd = nt * 4 + tg;
        if (row[0] < rows)
            outb[(size_t)row[0] * 32 + wrd] = cvt2(acc0[0] + b0v, acc0[1] + b1v);
        if (row[1] < rows)
            outb[(size_t)row[1] * 32 + wrd] = cvt2(acc0[2] + b0v, acc0[3] + b1v);
        if (row[2] < rows)
            outb[(size_t)row[2] * 32 + wrd] = cvt2(acc1[0] + b0v, acc1[1] + b1v);
        if (row[3] < rows)
            outb[(size_t)row[3] * 32 + wrd] = cvt2(acc1[2] + b0v, acc1[3] + b1v);
    }
}

// ============================================================
// edge_mlp_mma: per 256-edge tile (8 warps, 32 rows/warp = two m16 frags)
//   ALSO fills g_rs (rowptr) from its seg tile (boundary marking).
//   h = relu(Pb[nb] + Qb[sg])  (bf16x2 arith) -> smem tile (pitch 36 words)
//   A-fragments via ldmatrix.x4; D = h @ W2 via HMMA;
//   epilogue relu(D+b2).w3, 4-lane reduce, exp -> g_ex
// NOTE: gather loop unroll 2 only — full unroll under the 64-reg cap spills
// (R14 regression).
// ============================================================
__global__ void __launch_bounds__(256, 4) edge_mlp_mma(
    const int* __restrict__ neigh, const int* __restrict__ seg,
    const float* __restrict__ b2, const float* __restrict__ w3,
    const float* __restrict__ b3)
{
    __shared__ uint32_t sH[256 * 36];
    __shared__ int sIdx[512];

    int tid = threadIdx.x;
    int wid = tid >> 5, lane = tid & 31;
    int g = lane >> 2, tg = lane & 3;
    int e0 = blockIdx.x * 256;

    if (tid < 256) {
        int e = e0 + tid;
        int cur = __ldg(seg + e);
        sIdx[tid]       = __ldg(neigh + e);
        sIdx[256 + tid] = cur;
        // rowptr boundary marking (seg sorted)
        int prev = (e == 0) ? -1 : __ldg(seg + e - 1);
        for (int n = prev + 1; n <= cur; n++) g_rs[n] = e;
        if (e == EE - 1)
            for (int n = cur + 1; n <= NN; n++) g_rs[n] = EE;
    }
    __syncthreads();

    // gather bf16 rows + relu-add; each iter = one row's 8-value chunk (uint4)
#pragma unroll 2
    for (int i = tid; i < 2048; i += 256) {
        int r = i >> 3, c = i & 7;
        uint4 p = __ldg((const uint4*)(g_Pb + (size_t)sIdx[r]       * 32) + c);
        uint4 q = __ldg((const uint4*)(g_Qb + (size_t)sIdx[256 + r] * 32) + c);
        uint4 h;
        h.x = hreluadd2(p.x, q.x);
        h.y = hreluadd2(p.y, q.y);
        h.z = hreluadd2(p.z, q.z);
        h.w = hreluadd2(p.w, q.w);
        *(uint4*)(sH + r * 36 + c * 4) = h;
    }
    __syncthreads();

    // A-fragments via ldmatrix.x4: lanes 0-15 -> rows (k-lo half),
    // lanes 16-31 -> rows (k-hi half)
    int rb = wid * 32;
    uint32_t sbase = (uint32_t)__cvta_generic_to_shared(sH);
    int lrow = lane & 15, khalf = lane >> 4;
    uint32_t a0[4][4], a1[4][4];
#pragma unroll
    for (int ks = 0; ks < 4; ks++) {
        uint32_t off0 = ((rb + lrow) * 36 + ks * 8 + khalf * 4) * 4;
        ldsm_x4(a0[ks], sbase + off0);
        ldsm_x4(a1[ks], sbase + off0 + 16 * 36 * 4);
    }

    float s0 = 0.f, s1 = 0.f, s2 = 0.f, s3 = 0.f;
#pragma unroll
    for (int nt = 0; nt < 8; nt++) {
        const uint4* B = (const uint4*)(g_W2f + (nt * 32 + lane) * 8);
        uint4 bw0 = __ldg(B), bw1 = __ldg(B + 1);
        float acc0[4] = {0.f, 0.f, 0.f, 0.f};
        float acc1[4] = {0.f, 0.f, 0.f, 0.f};
        mma_1p_ntile(acc0, a0, bw0, bw1);
        mma_1p_ntile(acc1, a1, bw0, bw1);
        int c0 = nt * 8 + tg * 2;
        float2 bb = __ldg((const float2*)(b2 + c0));
        float2 ww = __ldg((const float2*)(w3 + c0));
        s0 += fmaxf(acc0[0] + bb.x, 0.f) * ww.x + fmaxf(acc0[1] + bb.y, 0.f) * ww.y;
        s1 += fmaxf(acc0[2] + bb.x, 0.f) * ww.x + fmaxf(acc0[3] + bb.y, 0.f) * ww.y;
        s2 += fmaxf(acc1[0] + bb.x, 0.f) * ww.x + fmaxf(acc1[1] + bb.y, 0.f) * ww.y;
        s3 += fmaxf(acc1[2] + bb.x, 0.f) * ww.x + fmaxf(acc1[3] + bb.y, 0.f) * ww.y;
    }
    s0 += __shfl_xor_sync(0xffffffffu, s0, 1);
    s0 += __shfl_xor_sync(0xffffffffu, s0, 2);
    s1 += __shfl_xor_sync(0xffffffffu, s1, 1);
    s1 += __shfl_xor_sync(0xffffffffu, s1, 2);
    s2 += __shfl_xor_sync(0xffffffffu, s2, 1);
    s2 += __shfl_xor_sync(0xffffffffu, s2, 2);
    s3 += __shfl_xor_sync(0xffffffffu, s3, 1);
    s3 += __shfl_xor_sync(0xffffffffu, s3, 2);
    if (tg == 0) {
        float b3v = __ldg(b3);
        g_ex[e0 + rb + g]      = expf(s0 + b3v);
        g_ex[e0 + rb + g + 8]  = expf(s1 + b3v);
        g_ex[e0 + rb + g + 16] = expf(s2 + b3v);
        g_ex[e0 + rb + g + 24] = expf(s3 + b3v);
    }
}

// ============================================================
// agg: one warp per node — row range from g_rs, single-pass weighted sum
// (denominator fused into the gather loop, scale at end);
// half-warp lanes (uint2 = 4 dims fp16), 8 edges in flight.
// ============================================================
__global__ void __launch_bounds__(256) agg_k(
    const int* __restrict__ nodes, const int* __restrict__ neigh,
    const float* __restrict__ u2e, float* __restrict__ out)
{
    int w = (blockIdx.x * 256 + threadIdx.x) >> 5;
    int lane = threadIdx.x & 31;
    if (w >= NN) return;
    int half = lane >> 4, l16 = lane & 15;

    int s = __ldg(g_rs + w), t = __ldg(g_rs + w + 1);

    if (s == t) {  // no neighbors: own embedding (exact fp32)
        int u = __ldg(nodes + w);
        if (half == 0) {
            float4 v = __ldg((const float4*)(u2e + (size_t)u * 64) + l16);
            *((float4*)(out + (size_t)w * 64) + l16) = v;
        }
        return;
    }

    float4 a = make_float4(0.f, 0.f, 0.f, 0.f);
    float4 b = make_float4(0.f, 0.f, 0.f, 0.f);
    float dsum = 0.f;  // identical across lanes of a half-warp
    int e = s;
    // 8 edges in flight per half-warp (16 edges per warp-iter)
    for (; e + 16 <= t; e += 16) {
        int   idx[8]; float wt[8]; uint2 v[8];
#pragma unroll
        for (int j = 0; j < 8; j++) {
            int ee = e + 2 * j + half;
            idx[j] = __ldg(neigh + ee);
            wt[j]  = __ldg(g_ex + ee);
        }
#pragma unroll
        for (int j = 0; j < 8; j++)
            v[j] = __ldg((const uint2*)(g_u2eh + (size_t)idx[j] * 64) + l16);
#pragma unroll
        for (int j = 0; j < 8; j += 2) {
            float4 f0 = h4tof4(v[j]), f1 = h4tof4(v[j + 1]);
            dsum += wt[j] + wt[j + 1];
            a.x = fmaf(wt[j], f0.x, a.x); a.y = fmaf(wt[j], f0.y, a.y);
            a.z = fmaf(wt[j], f0.z, a.z); a.w = fmaf(wt[j], f0.w, a.w);
            b.x = fmaf(wt[j+1], f1.x, b.x); b.y = fmaf(wt[j+1], f1.y, b.y);
            b.z = fmaf(wt[j+1], f1.z, b.z); b.w = fmaf(wt[j+1], f1.w, b.w);
        }
    }
    for (; e + 4 <= t; e += 4) {
        int   ea = e + half,          eb = e + 2 + half;
        int   na = __ldg(neigh + ea), nb = __ldg(neigh + eb);
        float wa = __ldg(g_ex + ea),  wb = __ldg(g_ex + eb);
        float4 va = h4tof4(__ldg((const uint2*)(g_u2eh + (size_t)na * 64) + l16));
        float4 vb = h4tof4(__ldg((const uint2*)(g_u2eh + (size_t)nb * 64) + l16));
        dsum += wa + wb;
        a.x = fmaf(wa, va.x, fmaf(wb, vb.x, a.x));
        a.y = fmaf(wa, va.y, fmaf(wb, vb.y, a.y));
        a.z = fmaf(wa, va.z, fmaf(wb, vb.z, a.z));
        a.w = fmaf(wa, va.w, fmaf(wb, vb.w, a.w));
    }
    for (; e < t; e += 2) {
        int ee = e + half;
        if (ee < t) {
            int   n0 = __ldg(neigh + ee);
            float w0 = __ldg(g_ex + ee);
            float4 v = h4tof4(__ldg((const uint2*)(g_u2eh + (size_t)n0 * 64) + l16));
            dsum += w0;
            a.x = fmaf(w0, v.x, a.x); a.y = fmaf(w0, v.y, a.y);
            a.z = fmaf(w0, v.z, a.z); a.w = fmaf(w0, v.w, a.w);
        }
    }
    a.x += b.x; a.y += b.y; a.z += b.z; a.w += b.w;
    // combine half-warps (dsum uniform within each half)
    dsum += __shfl_xor_sync(0xffffffffu, dsum, 16);
    a.x  += __shfl_xor_sync(0xffffffffu, a.x, 16);
    a.y  += __shfl_xor_sync(0xffffffffu, a.y, 16);
    a.z  += __shfl_xor_sync(0xffffffffu, a.z, 16);
    a.w  += __shfl_xor_sync(0xffffffffu, a.w, 16);
    if (half == 0) {
        float inv = 1.f / dsum;
        a.x *= inv; a.y *= inv; a.z *= inv; a.w *= inv;
        *((float4*)(out + (size_t)w * 64) + l16) = a;
    }
}

// ============================================================
extern "C" void kernel_launch(void* const* d_in, const int* in_sizes, int n_in,
                              void* d_out, int out_size)
{
    const int*   nodes = (const int*)d_in[0];
    const int*   neigh = (const int*)d_in[1];
    const int*   seg   = (const int*)d_in[2];
    const float* u2e   = (const float*)d_in[3];
    const float* W1    = (const float*)d_in[4];
    const float* b1    = (const float*)d_in[5];
    const float* W2    = (const float*)d_in[6];
    const float* b2    = (const float*)d_in[7];
    const float* w3    = (const float*)d_in[8];
    const float* b3    = (const float*)d_in[9];
    float* out = (float*)d_out;

    uint32_t *dPb, *dQb, *pW2, *pW1t, *pW1b;
    cudaGetSymbolAddress((void**)&dPb, g_Pb);
    cudaGetSymbolAddress((void**)&dQb, g_Qb);
    cudaGetSymbolAddress((void**)&pW2,  g_W2f);
    cudaGetSymbolAddress((void**)&pW1t, g_W1tf);
    cudaGetSymbolAddress((void**)&pW1b, g_W1bf);

    // weight packs (bf16, fragment order) — one fused launch
    prep_all<<<24, 256>>>(W1, W2);
    // P = bf16(u2e @ W1[:64]) + fused fp16 u2e copy
    rowgemm_mma<false, false, true><<<(UU + 255) / 256, 256>>>(
        u2e, nullptr, pW1t, nullptr, dPb, UU);
    // Q = bf16(u2e[nodes] @ W1[64:] + b1)
    rowgemm_mma<true, true, false><<<(NN + 255) / 256, 256>>>(
        u2e, nodes, pW1b, b1, dQb, NN);
    // per-edge MLP -> exp(logit)  (HMMA, ldmatrix frags, 256-edge tiles)
    // also fills g_rs (rowptr) from its seg tiles
    edge_mlp_mma<<<EE / 256, 256>>>(neigh, seg, b2, w3, b3);
    // segment softmax + weighted aggregation (+ zero-neighbor fallback)
    agg_k<<<(NN * 32 + 255) / 256, 256>>>(nodes, neigh, u2e, out);
}